// round 1
// baseline (speedup 1.0000x reference)
#include <cuda_runtime.h>
#include <math.h>

#define B_ 4
#define C_ 64
#define H_ 128
#define W_ 128
#define HW_ (H_*W_)
#define O_ 64

// Scratch (static device allocations are allowed)
__device__ __align__(16) float g_xt[B_*HW_*C_];     // x transposed to [b][h][w][c]
__device__ __align__(16) float g_off[B_*HW_*18];    // offsets per pixel [b][h][w][18]
__device__ __align__(16) float g_wdt[9*C_*O_];      // w_def reordered [k][c][o]
__device__ __align__(16) float g_partial[B_*H_*32]; // per-block GN partials [block][g][2]
__device__ __align__(16) float g_stats[B_*16*2];    // mu, inv_std per (b, group)

// ---------------- K0: NCHW -> NHWC transpose ----------------
__global__ void k_transpose(const float* __restrict__ x) {
    __shared__ float tile[32][33];
    int b  = blockIdx.z;
    int c0 = blockIdx.y * 32;
    int p0 = blockIdx.x * 32;
    int tx = threadIdx.x, ty = threadIdx.y;
    tile[ty][tx] = x[(b*C_ + c0 + ty)*HW_ + p0 + tx];
    __syncthreads();
    g_xt[(b*HW_ + p0 + ty)*C_ + c0 + tx] = tile[tx][ty];
}

// ---------------- Kw: w_def [o][c][3][3] -> [k][c][o] ----------------
__global__ void k_wreorder(const float* __restrict__ w_def) {
    int i = blockIdx.x * 256 + threadIdx.x;
    if (i < 9*64*64) {
        int o = i & 63;
        int c = (i >> 6) & 63;
        int k = i >> 12;
        g_wdt[i] = w_def[(o*64 + c)*9 + k];
    }
}

// ---------------- K1: offset conv (64 -> 18 channels, 3x3, pad 1) ----------------
// Block = one image row (b, h), 128 threads (one per pixel).
__global__ void __launch_bounds__(128) k_offconv(const float* __restrict__ x,
                                                 const float* __restrict__ w_off,
                                                 const float* __restrict__ b_off) {
    __shared__ __align__(16) float ws[64*9*20];   // padded 18 -> 20 for float4
    int h = blockIdx.x, b = blockIdx.y;
    int tid = threadIdx.x;

    for (int i = tid; i < 64*9*20; i += 128) ws[i] = 0.f;
    __syncthreads();
    for (int i = tid; i < 64*9*18; i += 128) {
        int o = i % 18;
        int cj = i / 18;           // cj = c*9 + j
        int c = cj / 9, j = cj % 9;
        ws[cj*20 + o] = w_off[(o*64 + c)*9 + j];
    }
    __syncthreads();

    int w = tid;
    float acc[20];
#pragma unroll
    for (int q = 0; q < 20; q++) acc[q] = 0.f;

    const float* xb = x + (size_t)b * C_ * HW_;
    bool wl = (w > 0), wr = (w < W_-1);

    for (int c = 0; c < C_; c++) {
        const float* xc = xb + c*HW_;
        float xv[9];
#pragma unroll
        for (int jy = 0; jy < 3; jy++) {
            int y = h + jy - 1;
            bool yv = (y >= 0 && y < H_);
            const float* row = xc + y*W_;
            xv[jy*3+0] = (yv && wl) ? row[w-1] : 0.f;
            xv[jy*3+1] =  yv        ? row[w]   : 0.f;
            xv[jy*3+2] = (yv && wr) ? row[w+1] : 0.f;
        }
#pragma unroll
        for (int j = 0; j < 9; j++) {
            const float4* wp4 = (const float4*)&ws[(c*9 + j)*20];
            float v = xv[j];
#pragma unroll
            for (int q4 = 0; q4 < 5; q4++) {
                float4 wv = wp4[q4];
                acc[q4*4+0] += wv.x * v;
                acc[q4*4+1] += wv.y * v;
                acc[q4*4+2] += wv.z * v;
                acc[q4*4+3] += wv.w * v;
            }
        }
    }

    float* op = &g_off[((size_t)(b*H_ + h)*W_ + w)*18];
#pragma unroll
    for (int o = 0; o < 18; o++) op[o] = acc[o] + b_off[o];
}

// ---------------- K2: deformable sample + GEMM + bias + GN partials ----------------
// Block = one image row (b, h). 256 threads.
// Stage A (per tap k): build samp[c][p] tile (64 x 128) in smem via bilinear gather from g_xt.
// Stage B: register-blocked GEMM: thread(r=tid/32, col=tid%32) owns 8 out-channels x 4 pixels.
__global__ void __launch_bounds__(256) k_main(const float* __restrict__ b_def,
                                              float* __restrict__ out) {
    __shared__ __align__(16) float s_samp[64*128]; // 32 KB
    __shared__ __align__(16) float s_wd[64*64];    // 16 KB  (total exactly 48 KB)

    int h = blockIdx.x, b = blockIdx.y;
    int tid = threadIdx.x;
    int p    = tid >> 1;
    int coff = (tid & 1) * 32;
    int r    = tid >> 5;
    int col  = tid & 31;

    float4 acc[8];
#pragma unroll
    for (int i = 0; i < 8; i++) acc[i] = make_float4(0.f, 0.f, 0.f, 0.f);

    const float* xb = g_xt + (size_t)b * HW_ * C_;
    const float* offp = &g_off[((size_t)(b*H_ + h)*W_ + p)*18];

#pragma unroll 1
    for (int k = 0; k < 9; k++) {
        // load tap weights [c][o]
        for (int i = tid; i < 4096; i += 256) s_wd[i] = g_wdt[k*4096 + i];

        // ---- stage A: bilinear sample 32 channels for pixel p ----
        float dy = offp[2*k], dx = offp[2*k + 1];
        float py = (float)(h + k/3 - 1) + dy;
        float px = (float)(p + k%3 - 1) + dx;
        float y0f = floorf(py), x0f = floorf(px);
        float wy = py - y0f, wx = px - x0f;
        int y0 = (int)y0f, x0 = (int)x0f;
        int y1 = y0 + 1, x1 = x0 + 1;
        float v00 = (y0 >= 0 && y0 < H_ && x0 >= 0 && x0 < W_) ? 1.f : 0.f;
        float v01 = (y0 >= 0 && y0 < H_ && x1 >= 0 && x1 < W_) ? 1.f : 0.f;
        float v10 = (y1 >= 0 && y1 < H_ && x0 >= 0 && x0 < W_) ? 1.f : 0.f;
        float v11 = (y1 >= 0 && y1 < H_ && x1 >= 0 && x1 < W_) ? 1.f : 0.f;
        float w00 = (1.f - wy) * (1.f - wx) * v00;
        float w01 = (1.f - wy) * wx * v01;
        float w10 = wy * (1.f - wx) * v10;
        float w11 = wy * wx * v11;
        int y0c = min(max(y0, 0), H_-1), y1c = min(max(y1, 0), H_-1);
        int x0c = min(max(x0, 0), W_-1), x1c = min(max(x1, 0), W_-1);
        const float4* p00 = (const float4*)(xb + (y0c*W_ + x0c)*C_ + coff);
        const float4* p01 = (const float4*)(xb + (y0c*W_ + x1c)*C_ + coff);
        const float4* p10 = (const float4*)(xb + (y1c*W_ + x0c)*C_ + coff);
        const float4* p11 = (const float4*)(xb + (y1c*W_ + x1c)*C_ + coff);
#pragma unroll
        for (int q = 0; q < 8; q++) {
            float4 a = p00[q], bb = p01[q], cc4 = p10[q], dd = p11[q];
            float sx = w00*a.x + w01*bb.x + w10*cc4.x + w11*dd.x;
            float sy = w00*a.y + w01*bb.y + w10*cc4.y + w11*dd.y;
            float sz = w00*a.z + w01*bb.z + w10*cc4.z + w11*dd.z;
            float sw = w00*a.w + w01*bb.w + w10*cc4.w + w11*dd.w;
            int cbase = coff + q*4;
            s_samp[(cbase+0)*128 + p] = sx;
            s_samp[(cbase+1)*128 + p] = sy;
            s_samp[(cbase+2)*128 + p] = sz;
            s_samp[(cbase+3)*128 + p] = sw;
        }
        __syncthreads();

        // ---- stage B: accumulate out[8o][4p] ----
#pragma unroll 8
        for (int c = 0; c < 64; c++) {
            float4 s4 = *(const float4*)&s_samp[c*128 + col*4];
            float4 wa = *(const float4*)&s_wd[c*64 + r*8];
            float4 wb = *(const float4*)&s_wd[c*64 + r*8 + 4];
            acc[0].x += wa.x*s4.x; acc[0].y += wa.x*s4.y; acc[0].z += wa.x*s4.z; acc[0].w += wa.x*s4.w;
            acc[1].x += wa.y*s4.x; acc[1].y += wa.y*s4.y; acc[1].z += wa.y*s4.z; acc[1].w += wa.y*s4.w;
            acc[2].x += wa.z*s4.x; acc[2].y += wa.z*s4.y; acc[2].z += wa.z*s4.z; acc[2].w += wa.z*s4.w;
            acc[3].x += wa.w*s4.x; acc[3].y += wa.w*s4.y; acc[3].z += wa.w*s4.z; acc[3].w += wa.w*s4.w;
            acc[4].x += wb.x*s4.x; acc[4].y += wb.x*s4.y; acc[4].z += wb.x*s4.z; acc[4].w += wb.x*s4.w;
            acc[5].x += wb.y*s4.x; acc[5].y += wb.y*s4.y; acc[5].z += wb.y*s4.z; acc[5].w += wb.y*s4.w;
            acc[6].x += wb.z*s4.x; acc[6].y += wb.z*s4.y; acc[6].z += wb.z*s4.z; acc[6].w += wb.z*s4.w;
            acc[7].x += wb.w*s4.x; acc[7].y += wb.w*s4.y; acc[7].z += wb.w*s4.z; acc[7].w += wb.w*s4.w;
        }
        __syncthreads();
    }

    // ---- epilogue: bias, write pre-GN output, per-group partial sums ----
    float s0 = 0.f, q0 = 0.f, s1 = 0.f, q1 = 0.f;
    float* outb = out + (size_t)b * O_ * HW_ + h*W_ + col*4;
#pragma unroll
    for (int i = 0; i < 8; i++) {
        int o = r*8 + i;
        float bo = b_def[o];
        float4 v = acc[i];
        v.x += bo; v.y += bo; v.z += bo; v.w += bo;
        *(float4*)(outb + (size_t)o * HW_) = v;
        float sv = v.x + v.y + v.z + v.w;
        float sq = v.x*v.x + v.y*v.y + v.z*v.z + v.w*v.w;
        if (i < 4) { s0 += sv; q0 += sq; } else { s1 += sv; q1 += sq; }
    }
#pragma unroll
    for (int off = 16; off > 0; off >>= 1) {
        s0 += __shfl_xor_sync(0xffffffffu, s0, off);
        q0 += __shfl_xor_sync(0xffffffffu, q0, off);
        s1 += __shfl_xor_sync(0xffffffffu, s1, off);
        q1 += __shfl_xor_sync(0xffffffffu, q1, off);
    }
    if (col == 0) {
        // warp r covers groups 2r and 2r+1 (o = r*8 .. r*8+7)
        float* pp = &g_partial[(size_t)(b*H_ + h)*32];
        pp[(2*r  )*2 + 0] = s0;
        pp[(2*r  )*2 + 1] = q0;
        pp[(2*r+1)*2 + 0] = s1;
        pp[(2*r+1)*2 + 1] = q1;
    }
}

// ---------------- K3: finalize GN stats (deterministic fixed-order sum) ----------------
__global__ void k_stats() {
    int t = threadIdx.x;
    if (t >= 64) return;
    int b = t >> 4, g = t & 15;
    float s = 0.f, q = 0.f;
    for (int blk = 0; blk < H_; blk++) {
        const float* pp = &g_partial[(size_t)(b*H_ + blk)*32 + g*2];
        s += pp[0];
        q += pp[1];
    }
    const float N = 4.f * (float)HW_;   // 4 channels per group * H * W
    float mu = s / N;
    float var = q / N - mu*mu;
    g_stats[t*2 + 0] = mu;
    g_stats[t*2 + 1] = rsqrtf(var + 1e-5f);
}

// ---------------- K4: GroupNorm affine + LeakyReLU (in-place on d_out) ----------------
__global__ void k_norm(float* __restrict__ out,
                       const float* __restrict__ gn_w,
                       const float* __restrict__ gn_b) {
    int i = blockIdx.x * 256 + threadIdx.x;      // float4 index
    int base = i * 4;
    int c = (base >> 14) & 63;                   // HW_ = 16384
    int b = base >> 20;                          // C_*HW_ = 1048576
    int g = c >> 2;
    float mu  = g_stats[(b*16 + g)*2 + 0];
    float inv = g_stats[(b*16 + g)*2 + 1];
    float sc = gn_w[c] * inv;
    float sh = gn_b[c] - mu * sc;
    float4 v = ((float4*)out)[i];
    v.x = v.x*sc + sh; v.x = (v.x >= 0.f) ? v.x : 0.2f*v.x;
    v.y = v.y*sc + sh; v.y = (v.y >= 0.f) ? v.y : 0.2f*v.y;
    v.z = v.z*sc + sh; v.z = (v.z >= 0.f) ? v.z : 0.2f*v.z;
    v.w = v.w*sc + sh; v.w = (v.w >= 0.f) ? v.w : 0.2f*v.w;
    ((float4*)out)[i] = v;
}

extern "C" void kernel_launch(void* const* d_in, const int* in_sizes, int n_in,
                              void* d_out, int out_size) {
    const float* x     = (const float*)d_in[0];
    const float* w_off = (const float*)d_in[1];
    const float* b_off = (const float*)d_in[2];
    const float* w_def = (const float*)d_in[3];
    const float* b_def = (const float*)d_in[4];
    const float* gn_w  = (const float*)d_in[5];
    const float* gn_b  = (const float*)d_in[6];
    float* out = (float*)d_out;

    k_transpose<<<dim3(HW_/32, C_/32, B_), dim3(32, 32)>>>(x);
    k_wreorder<<<144, 256>>>(w_def);
    k_offconv<<<dim3(H_, B_), 128>>>(x, w_off, b_off);
    k_main<<<dim3(H_, B_), 256>>>(b_def, out);
    k_stats<<<1, 64>>>();
    k_norm<<<4096, 256>>>(out, gn_w, gn_b);
}

// round 2
// speedup vs baseline: 1.0213x; 1.0213x over previous
#include <cuda_runtime.h>
#include <math.h>

#define B_ 4
#define C_ 64
#define H_ 128
#define W_ 128
#define HW_ (H_*W_)
#define O_ 64

// Packed f32x2 helpers (Blackwell sm_100a+)
#define FMA2(acc, a, b) asm("fma.rn.f32x2 %0, %1, %2, %0;" : "+l"(acc) : "l"(a), "l"(b))
#define DUP2(dst, f)    asm("mov.b64 %0, {%1, %1};" : "=l"(dst) : "f"(f))
#define UNPK2(lo, hi, v) asm("mov.b64 {%0, %1}, %2;" : "=f"(lo), "=f"(hi) : "l"(v))

// Scratch (static device allocations are allowed)
__device__ __align__(16) float g_xt[B_*HW_*C_];     // x transposed to [b][h][w][c]
__device__ __align__(16) float g_off[B_*HW_*18];    // offsets per pixel [b][h][w][18]
__device__ __align__(16) float g_wdt[9*C_*O_];      // w_def reordered [k][c][o]
__device__ __align__(16) float g_partial[B_*H_*32]; // per-block GN partials [block][g][2]
__device__ __align__(16) float g_stats[B_*16*2];    // mu, inv_std per (b, group)

// ---------------- K0: NCHW -> NHWC transpose ----------------
__global__ void k_transpose(const float* __restrict__ x) {
    __shared__ float tile[32][33];
    int b  = blockIdx.z;
    int c0 = blockIdx.y * 32;
    int p0 = blockIdx.x * 32;
    int tx = threadIdx.x, ty = threadIdx.y;
    tile[ty][tx] = x[(b*C_ + c0 + ty)*HW_ + p0 + tx];
    __syncthreads();
    g_xt[(b*HW_ + p0 + ty)*C_ + c0 + tx] = tile[tx][ty];
}

// ---------------- Kw: w_def [o][c][3][3] -> [k][c][o] ----------------
__global__ void k_wreorder(const float* __restrict__ w_def) {
    int i = blockIdx.x * 256 + threadIdx.x;
    if (i < 9*64*64) {
        int o = i & 63;
        int c = (i >> 6) & 63;
        int k = i >> 12;
        g_wdt[i] = w_def[(o*64 + c)*9 + k];
    }
}

// ---------------- K1: offset conv (64 -> 18 channels, 3x3, pad 1) ----------------
// Block = one image row (b, h), 128 threads (one per pixel). f32x2 packed accumulators.
__global__ void __launch_bounds__(128) k_offconv(const float* __restrict__ x,
                                                 const float* __restrict__ w_off,
                                                 const float* __restrict__ b_off) {
    __shared__ __align__(16) float ws[64*9*20];   // padded 18 -> 20 for vector loads
    int h = blockIdx.x, b = blockIdx.y;
    int tid = threadIdx.x;

    for (int i = tid; i < 64*9*20; i += 128) ws[i] = 0.f;
    __syncthreads();
    for (int i = tid; i < 64*9*18; i += 128) {
        int o = i % 18;
        int cj = i / 18;           // cj = c*9 + j
        int c = cj / 9, j = cj % 9;
        ws[cj*20 + o] = w_off[(o*64 + c)*9 + j];
    }
    __syncthreads();

    int w = tid;
    unsigned long long acc[10];
#pragma unroll
    for (int q = 0; q < 10; q++) acc[q] = 0ull;

    const float* xb = x + (size_t)b * C_ * HW_;
    bool wl = (w > 0), wr = (w < W_-1);

    for (int c = 0; c < C_; c++) {
        const float* xc = xb + c*HW_;
        float xv[9];
#pragma unroll
        for (int jy = 0; jy < 3; jy++) {
            int y = h + jy - 1;
            bool yv = (y >= 0 && y < H_);
            const float* row = xc + y*W_;
            xv[jy*3+0] = (yv && wl) ? row[w-1] : 0.f;
            xv[jy*3+1] =  yv        ? row[w]   : 0.f;
            xv[jy*3+2] = (yv && wr) ? row[w+1] : 0.f;
        }
#pragma unroll
        for (int j = 0; j < 9; j++) {
            unsigned long long v2;
            DUP2(v2, xv[j]);
            const ulonglong2* wp = (const ulonglong2*)&ws[(c*9 + j)*20];
#pragma unroll
            for (int q = 0; q < 5; q++) {
                ulonglong2 wv = wp[q];
                FMA2(acc[2*q+0], wv.x, v2);
                FMA2(acc[2*q+1], wv.y, v2);
            }
        }
    }

    float* op = &g_off[((size_t)(b*H_ + h)*W_ + w)*18];
#pragma unroll
    for (int q = 0; q < 9; q++) {
        float lo, hi;
        UNPK2(lo, hi, acc[q]);
        op[2*q+0] = lo + b_off[2*q+0];
        op[2*q+1] = hi + b_off[2*q+1];
    }
}

// ---------------- K2: deformable sample + GEMM + bias + GN partials ----------------
// Block = one image row (b, h). 256 threads, 3 blocks/SM.
// Stage A (per tap k): build samp[c][p] tile (64 x 128) in smem via bilinear gather from g_xt.
// Stage B: f32x2 register-blocked GEMM: thread(r,col) owns 8 out-channels x 4 pixels
//          (2 packed pixel-pairs per out-channel).
__global__ void __launch_bounds__(256, 3) k_main(const float* __restrict__ b_def,
                                                 float* __restrict__ out) {
    __shared__ __align__(16) float s_samp[64*128]; // 32 KB
    __shared__ __align__(16) float s_wd[64*64];    // 16 KB  (total exactly 48 KB)

    int h = blockIdx.x, b = blockIdx.y;
    int tid = threadIdx.x;
    int p    = tid >> 1;
    int coff = (tid & 1) * 32;
    int r    = tid >> 5;
    int col  = tid & 31;

    unsigned long long acc[8][2];
#pragma unroll
    for (int i = 0; i < 8; i++) { acc[i][0] = 0ull; acc[i][1] = 0ull; }

    const float* xb = g_xt + (size_t)b * HW_ * C_;
    const float* offp = &g_off[((size_t)(b*H_ + h)*W_ + p)*18];

#pragma unroll 1
    for (int k = 0; k < 9; k++) {
        // load tap weights [c][o]
        {
            const float4* src = (const float4*)(g_wdt + k*4096);
            float4* dst = (float4*)s_wd;
            for (int i = tid; i < 1024; i += 256) dst[i] = src[i];
        }

        // ---- stage A: bilinear sample 32 channels for pixel p ----
        float dy = offp[2*k], dx = offp[2*k + 1];
        float py = (float)(h + k/3 - 1) + dy;
        float px = (float)(p + k%3 - 1) + dx;
        float y0f = floorf(py), x0f = floorf(px);
        float wy = py - y0f, wx = px - x0f;
        int y0 = (int)y0f, x0 = (int)x0f;
        int y1 = y0 + 1, x1 = x0 + 1;
        float v00 = (y0 >= 0 && y0 < H_ && x0 >= 0 && x0 < W_) ? 1.f : 0.f;
        float v01 = (y0 >= 0 && y0 < H_ && x1 >= 0 && x1 < W_) ? 1.f : 0.f;
        float v10 = (y1 >= 0 && y1 < H_ && x0 >= 0 && x0 < W_) ? 1.f : 0.f;
        float v11 = (y1 >= 0 && y1 < H_ && x1 >= 0 && x1 < W_) ? 1.f : 0.f;
        float w00 = (1.f - wy) * (1.f - wx) * v00;
        float w01 = (1.f - wy) * wx * v01;
        float w10 = wy * (1.f - wx) * v10;
        float w11 = wy * wx * v11;
        int y0c = min(max(y0, 0), H_-1), y1c = min(max(y1, 0), H_-1);
        int x0c = min(max(x0, 0), W_-1), x1c = min(max(x1, 0), W_-1);
        const float4* p00 = (const float4*)(xb + (y0c*W_ + x0c)*C_ + coff);
        const float4* p01 = (const float4*)(xb + (y0c*W_ + x1c)*C_ + coff);
        const float4* p10 = (const float4*)(xb + (y1c*W_ + x0c)*C_ + coff);
        const float4* p11 = (const float4*)(xb + (y1c*W_ + x1c)*C_ + coff);
#pragma unroll
        for (int q = 0; q < 8; q++) {
            float4 a = p00[q], bb = p01[q], cc4 = p10[q], dd = p11[q];
            float sx = w00*a.x + w01*bb.x + w10*cc4.x + w11*dd.x;
            float sy = w00*a.y + w01*bb.y + w10*cc4.y + w11*dd.y;
            float sz = w00*a.z + w01*bb.z + w10*cc4.z + w11*dd.z;
            float sw = w00*a.w + w01*bb.w + w10*cc4.w + w11*dd.w;
            int cbase = coff + q*4;
            s_samp[(cbase+0)*128 + p] = sx;
            s_samp[(cbase+1)*128 + p] = sy;
            s_samp[(cbase+2)*128 + p] = sz;
            s_samp[(cbase+3)*128 + p] = sw;
        }
        __syncthreads();

        // ---- stage B: f32x2 GEMM, 8 o x 2 pixel-pairs per thread ----
#pragma unroll 8
        for (int c = 0; c < 64; c++) {
            ulonglong2 s2 = *(const ulonglong2*)&s_samp[c*128 + col*4];
            float4 wa = *(const float4*)&s_wd[c*64 + r*8];
            float4 wb = *(const float4*)&s_wd[c*64 + r*8 + 4];
            unsigned long long w0, w1, w2, w3, w4, w5, w6, w7;
            DUP2(w0, wa.x); DUP2(w1, wa.y); DUP2(w2, wa.z); DUP2(w3, wa.w);
            DUP2(w4, wb.x); DUP2(w5, wb.y); DUP2(w6, wb.z); DUP2(w7, wb.w);
            FMA2(acc[0][0], w0, s2.x); FMA2(acc[0][1], w0, s2.y);
            FMA2(acc[1][0], w1, s2.x); FMA2(acc[1][1], w1, s2.y);
            FMA2(acc[2][0], w2, s2.x); FMA2(acc[2][1], w2, s2.y);
            FMA2(acc[3][0], w3, s2.x); FMA2(acc[3][1], w3, s2.y);
            FMA2(acc[4][0], w4, s2.x); FMA2(acc[4][1], w4, s2.y);
            FMA2(acc[5][0], w5, s2.x); FMA2(acc[5][1], w5, s2.y);
            FMA2(acc[6][0], w6, s2.x); FMA2(acc[6][1], w6, s2.y);
            FMA2(acc[7][0], w7, s2.x); FMA2(acc[7][1], w7, s2.y);
        }
        __syncthreads();
    }

    // ---- epilogue: bias, write pre-GN output, per-group partial sums ----
    float s0 = 0.f, q0 = 0.f, s1 = 0.f, q1 = 0.f;
    float* outb = out + (size_t)b * O_ * HW_ + h*W_ + col*4;
#pragma unroll
    for (int i = 0; i < 8; i++) {
        int o = r*8 + i;
        float bo = b_def[o];
        float4 v;
        UNPK2(v.x, v.y, acc[i][0]);
        UNPK2(v.z, v.w, acc[i][1]);
        v.x += bo; v.y += bo; v.z += bo; v.w += bo;
        *(float4*)(outb + (size_t)o * HW_) = v;
        float sv = v.x + v.y + v.z + v.w;
        float sq = v.x*v.x + v.y*v.y + v.z*v.z + v.w*v.w;
        if (i < 4) { s0 += sv; q0 += sq; } else { s1 += sv; q1 += sq; }
    }
#pragma unroll
    for (int off = 16; off > 0; off >>= 1) {
        s0 += __shfl_xor_sync(0xffffffffu, s0, off);
        q0 += __shfl_xor_sync(0xffffffffu, q0, off);
        s1 += __shfl_xor_sync(0xffffffffu, s1, off);
        q1 += __shfl_xor_sync(0xffffffffu, q1, off);
    }
    if (col == 0) {
        float* pp = &g_partial[(size_t)(b*H_ + h)*32];
        pp[(2*r  )*2 + 0] = s0;
        pp[(2*r  )*2 + 1] = q0;
        pp[(2*r+1)*2 + 0] = s1;
        pp[(2*r+1)*2 + 1] = q1;
    }
}

// ---------------- K3: finalize GN stats (deterministic fixed-order sum) ----------------
__global__ void k_stats() {
    int t = threadIdx.x;
    if (t >= 64) return;
    int b = t >> 4, g = t & 15;
    float s = 0.f, q = 0.f;
    for (int blk = 0; blk < H_; blk++) {
        const float* pp = &g_partial[(size_t)(b*H_ + blk)*32 + g*2];
        s += pp[0];
        q += pp[1];
    }
    const float N = 4.f * (float)HW_;   // 4 channels per group * H * W
    float mu = s / N;
    float var = q / N - mu*mu;
    g_stats[t*2 + 0] = mu;
    g_stats[t*2 + 1] = rsqrtf(var + 1e-5f);
}

// ---------------- K4: GroupNorm affine + LeakyReLU (in-place on d_out) ----------------
__global__ void k_norm(float* __restrict__ out,
                       const float* __restrict__ gn_w,
                       const float* __restrict__ gn_b) {
    int i = blockIdx.x * 256 + threadIdx.x;      // float4 index
    int base = i * 4;
    int c = (base >> 14) & 63;                   // HW_ = 16384
    int b = base >> 20;                          // C_*HW_ = 1048576
    int g = c >> 2;
    float mu  = g_stats[(b*16 + g)*2 + 0];
    float inv = g_stats[(b*16 + g)*2 + 1];
    float sc = gn_w[c] * inv;
    float sh = gn_b[c] - mu * sc;
    float4 v = ((float4*)out)[i];
    v.x = v.x*sc + sh; v.x = (v.x >= 0.f) ? v.x : 0.2f*v.x;
    v.y = v.y*sc + sh; v.y = (v.y >= 0.f) ? v.y : 0.2f*v.y;
    v.z = v.z*sc + sh; v.z = (v.z >= 0.f) ? v.z : 0.2f*v.z;
    v.w = v.w*sc + sh; v.w = (v.w >= 0.f) ? v.w : 0.2f*v.w;
    ((float4*)out)[i] = v;
}

extern "C" void kernel_launch(void* const* d_in, const int* in_sizes, int n_in,
                              void* d_out, int out_size) {
    const float* x     = (const float*)d_in[0];
    const float* w_off = (const float*)d_in[1];
    const float* b_off = (const float*)d_in[2];
    const float* w_def = (const float*)d_in[3];
    const float* b_def = (const float*)d_in[4];
    const float* gn_w  = (const float*)d_in[5];
    const float* gn_b  = (const float*)d_in[6];
    float* out = (float*)d_out;

    k_transpose<<<dim3(HW_/32, C_/32, B_), dim3(32, 32)>>>(x);
    k_wreorder<<<144, 256>>>(w_def);
    k_offconv<<<dim3(H_, B_), 128>>>(x, w_off, b_off);
    k_main<<<dim3(H_, B_), 256>>>(b_def, out);
    k_stats<<<1, 64>>>();
    k_norm<<<4096, 256>>>(out, gn_w, gn_b);
}

// round 3
// speedup vs baseline: 1.3220x; 1.2945x over previous
#include <cuda_runtime.h>
#include <math.h>

#define B_ 4
#define C_ 64
#define H_ 128
#define W_ 128
#define HW_ (H_*W_)
#define O_ 64

// Packed f32x2 helpers (Blackwell)
#define FMA2(acc, a, b) asm("fma.rn.f32x2 %0, %1, %2, %0;" : "+l"(acc) : "l"(a), "l"(b))
#define DUP2(dst, f)    asm("mov.b64 %0, {%1, %1};" : "=l"(dst) : "f"(f))
#define UNPK2(lo, hi, v) asm("mov.b64 {%0, %1}, %2;" : "=f"(lo), "=f"(hi) : "l"(v))

// Scratch
__device__ __align__(16) float g_xt[B_*HW_*C_];       // x in NHWC
__device__ __align__(16) float g_off[B_*HW_*18];      // offsets [b][h][w][18]
__device__ __align__(16) float g_wdt[9*C_*O_];        // w_def [k][c][o]
__device__ __align__(16) float g_partial[256*2*16*2]; // [blk][half][group][2]
__device__ __align__(16) float g_stats[B_*16*2];      // mu, inv_std

// ---------------- K0: NCHW -> NHWC transpose ----------------
__global__ void k_transpose(const float* __restrict__ x) {
    __shared__ float tile[32][33];
    int b  = blockIdx.z;
    int c0 = blockIdx.y * 32;
    int p0 = blockIdx.x * 32;
    int tx = threadIdx.x, ty = threadIdx.y;
    tile[ty][tx] = x[(b*C_ + c0 + ty)*HW_ + p0 + tx];
    __syncthreads();
    g_xt[(b*HW_ + p0 + ty)*C_ + c0 + tx] = tile[tx][ty];
}

// ---------------- Kw: w_def [o][c][3][3] -> [k][c][o] ----------------
__global__ void k_wreorder(const float* __restrict__ w_def) {
    int i = blockIdx.x * 256 + threadIdx.x;
    if (i < 9*64*64) {
        int o = i & 63;
        int c = (i >> 6) & 63;
        int k = i >> 12;
        g_wdt[i] = w_def[(o*64 + c)*9 + k];
    }
}

// ---------------- K1: offset conv (64 -> 18 ch, 3x3, pad 1) ----------------
__global__ void __launch_bounds__(128) k_offconv(const float* __restrict__ x,
                                                 const float* __restrict__ w_off,
                                                 const float* __restrict__ b_off) {
    __shared__ __align__(16) float ws[64*9*20];
    int h = blockIdx.x, b = blockIdx.y;
    int tid = threadIdx.x;

    for (int i = tid; i < 64*9*20; i += 128) ws[i] = 0.f;
    __syncthreads();
    for (int i = tid; i < 64*9*18; i += 128) {
        int o = i % 18;
        int cj = i / 18;
        int c = cj / 9, j = cj % 9;
        ws[cj*20 + o] = w_off[(o*64 + c)*9 + j];
    }
    __syncthreads();

    int w = tid;
    unsigned long long acc[10];
#pragma unroll
    for (int q = 0; q < 10; q++) acc[q] = 0ull;

    const float* xb = x + (size_t)b * C_ * HW_;
    bool wl = (w > 0), wr = (w < W_-1);

    for (int c = 0; c < C_; c++) {
        const float* xc = xb + c*HW_;
        float xv[9];
#pragma unroll
        for (int jy = 0; jy < 3; jy++) {
            int y = h + jy - 1;
            bool yv = (y >= 0 && y < H_);
            const float* row = xc + y*W_;
            xv[jy*3+0] = (yv && wl) ? row[w-1] : 0.f;
            xv[jy*3+1] =  yv        ? row[w]   : 0.f;
            xv[jy*3+2] = (yv && wr) ? row[w+1] : 0.f;
        }
#pragma unroll
        for (int j = 0; j < 9; j++) {
            unsigned long long v2;
            DUP2(v2, xv[j]);
            const ulonglong2* wp = (const ulonglong2*)&ws[(c*9 + j)*20];
#pragma unroll
            for (int q = 0; q < 5; q++) {
                ulonglong2 wv = wp[q];
                FMA2(acc[2*q+0], wv.x, v2);
                FMA2(acc[2*q+1], wv.y, v2);
            }
        }
    }

    float* op = &g_off[((size_t)(b*H_ + h)*W_ + w)*18];
#pragma unroll
    for (int q = 0; q < 9; q++) {
        float lo, hi;
        UNPK2(lo, hi, acc[q]);
        op[2*q+0] = lo + b_off[2*q+0];
        op[2*q+1] = hi + b_off[2*q+1];
    }
}

// ---------------- K2: deformable sample + GEMM + bias + GN partials ----------------
// Block = 2 image rows (256 px), 256 threads, 2 blocks/SM (single wave of 256 blocks).
// smem (dynamic, floats):
//   s_samp [64][256] swizzled : 16384 f
//   s_wd   [64][64]           :  4096 f
//   s_addr [4][256] (int)     :  1024
//   s_w    [4][256]           :  1024
#define SM_WD   16384
#define SM_ADDR 20480
#define SM_WGT  21504
#define SM_TOTF 22528

__global__ void __launch_bounds__(256, 2) k_main(const float* __restrict__ b_def,
                                                 float* __restrict__ out) {
    extern __shared__ float sm[];
    float* s_samp = sm;
    float* s_wd   = sm + SM_WD;
    int*   s_addr = (int*)(sm + SM_ADDR);
    float* s_w    = sm + SM_WGT;

    int hb = blockIdx.x;          // row pair
    int b  = blockIdx.y;
    int tid = threadIdx.x;
    int warp = tid >> 5, col = tid & 31;
    int g = tid >> 4, l = tid & 15;

    int half = warp >> 2;         // which row of the pair this warp's GEMM covers
    int o0 = (warp & 3) * 16;     // 16 out-channels per warp
    int i4 = (half*32 + col);     // p>>2 for this thread's 4 pixels

    // A1 pixel for this thread
    int row_a = tid >> 7;
    int w_a = tid & 127;
    int h_a = hb*2 + row_a;
    const float* offp = g_off + ((size_t)((b*H_ + h_a)*W_) + w_a)*18;
    const float* xb = g_xt + (size_t)b * HW_ * C_;

    unsigned long long acc[16][2];
#pragma unroll
    for (int i = 0; i < 16; i++) { acc[i][0] = 0ull; acc[i][1] = 0ull; }

#pragma unroll 1
    for (int k = 0; k < 9; k++) {
        __syncthreads();
        // ---- A1: corner addresses + bilinear weights for this tap ----
        {
            float dy = offp[2*k], dx = offp[2*k+1];
            float py  = (float)(h_a + k/3 - 1) + dy;
            float pxf = (float)(w_a + k%3 - 1) + dx;
            float y0f = floorf(py), x0f = floorf(pxf);
            float wy = py - y0f, wx = pxf - x0f;
            int y0 = (int)y0f, x0 = (int)x0f;
            int y1 = y0 + 1, x1 = x0 + 1;
            float vy0 = (y0 >= 0 && y0 < H_) ? 1.f : 0.f;
            float vy1 = (y1 >= 0 && y1 < H_) ? 1.f : 0.f;
            float vx0 = (x0 >= 0 && x0 < W_) ? 1.f : 0.f;
            float vx1 = (x1 >= 0 && x1 < W_) ? 1.f : 0.f;
            int y0c = min(max(y0,0),H_-1), y1c = min(max(y1,0),H_-1);
            int x0c = min(max(x0,0),W_-1), x1c = min(max(x1,0),W_-1);
            s_addr[0*256+tid] = (y0c*W_ + x0c)*C_;  s_w[0*256+tid] = (1.f-wy)*(1.f-wx)*vy0*vx0;
            s_addr[1*256+tid] = (y0c*W_ + x1c)*C_;  s_w[1*256+tid] = (1.f-wy)*wx*vy0*vx1;
            s_addr[2*256+tid] = (y1c*W_ + x0c)*C_;  s_w[2*256+tid] = wy*(1.f-wx)*vy1*vx0;
            s_addr[3*256+tid] = (y1c*W_ + x1c)*C_;  s_w[3*256+tid] = wy*wx*vy1*vx1;
        }
        // ---- copy tap weights ----
        {
            const float4* src = (const float4*)(g_wdt + k*4096);
            float4* dst = (float4*)s_wd;
#pragma unroll
            for (int i = 0; i < 4; i++) dst[tid + i*256] = src[tid + i*256];
        }
        __syncthreads();

        // ---- A2: cooperative gather -> s_samp (16 lanes per pixel, lane l = ch 4l..4l+3)
#pragma unroll 2
        for (int ii = 0; ii < 16; ii++) {
            int pxi = ii*16 + g;
            float sx = 0.f, sy = 0.f, sz = 0.f, sw = 0.f;
#pragma unroll
            for (int corner = 0; corner < 4; corner++) {
                int a = s_addr[corner*256 + pxi];
                float wgt = s_w[corner*256 + pxi];
                const float4 v = *(const float4*)(xb + a + l*4);
                sx += wgt*v.x; sy += wgt*v.y; sz += wgt*v.z; sw += wgt*v.w;
            }
            int idx4 = (pxi >> 2) ^ l;
            float* dst = &s_samp[(l*4)*256 + idx4*4 + (pxi & 3)];
            dst[0]   = sx;
            dst[256] = sy;
            dst[512] = sz;
            dst[768] = sw;
        }
        __syncthreads();

        // ---- B: 16o x 4p register-blocked GEMM ----
#pragma unroll 4
        for (int c = 0; c < 64; c++) {
            int idx4 = i4 ^ (c >> 2);
            ulonglong2 s2 = *(const ulonglong2*)&s_samp[c*256 + idx4*4];
            float4 wa = *(const float4*)&s_wd[c*64 + o0];
            float4 wb = *(const float4*)&s_wd[c*64 + o0 + 4];
            float4 wc = *(const float4*)&s_wd[c*64 + o0 + 8];
            float4 wd = *(const float4*)&s_wd[c*64 + o0 + 12];
            unsigned long long d0,d1,d2,d3;
            DUP2(d0, wa.x); DUP2(d1, wa.y); DUP2(d2, wa.z); DUP2(d3, wa.w);
            FMA2(acc[0][0], d0, s2.x); FMA2(acc[0][1], d0, s2.y);
            FMA2(acc[1][0], d1, s2.x); FMA2(acc[1][1], d1, s2.y);
            FMA2(acc[2][0], d2, s2.x); FMA2(acc[2][1], d2, s2.y);
            FMA2(acc[3][0], d3, s2.x); FMA2(acc[3][1], d3, s2.y);
            DUP2(d0, wb.x); DUP2(d1, wb.y); DUP2(d2, wb.z); DUP2(d3, wb.w);
            FMA2(acc[4][0], d0, s2.x); FMA2(acc[4][1], d0, s2.y);
            FMA2(acc[5][0], d1, s2.x); FMA2(acc[5][1], d1, s2.y);
            FMA2(acc[6][0], d2, s2.x); FMA2(acc[6][1], d2, s2.y);
            FMA2(acc[7][0], d3, s2.x); FMA2(acc[7][1], d3, s2.y);
            DUP2(d0, wc.x); DUP2(d1, wc.y); DUP2(d2, wc.z); DUP2(d3, wc.w);
            FMA2(acc[8][0],  d0, s2.x); FMA2(acc[8][1],  d0, s2.y);
            FMA2(acc[9][0],  d1, s2.x); FMA2(acc[9][1],  d1, s2.y);
            FMA2(acc[10][0], d2, s2.x); FMA2(acc[10][1], d2, s2.y);
            FMA2(acc[11][0], d3, s2.x); FMA2(acc[11][1], d3, s2.y);
            DUP2(d0, wd.x); DUP2(d1, wd.y); DUP2(d2, wd.z); DUP2(d3, wd.w);
            FMA2(acc[12][0], d0, s2.x); FMA2(acc[12][1], d0, s2.y);
            FMA2(acc[13][0], d1, s2.x); FMA2(acc[13][1], d1, s2.y);
            FMA2(acc[14][0], d2, s2.x); FMA2(acc[14][1], d2, s2.y);
            FMA2(acc[15][0], d3, s2.x); FMA2(acc[15][1], d3, s2.y);
        }
    }

    // ---- epilogue: bias, store pre-GN, per-group partials ----
    float sg[4] = {0,0,0,0}, qg[4] = {0,0,0,0};
    int h_out = hb*2 + half;
    float* outb = out + (size_t)b * O_ * HW_ + h_out*W_ + col*4;
#pragma unroll
    for (int i = 0; i < 16; i++) {
        int o = o0 + i;
        float bo = b_def[o];
        float4 v;
        UNPK2(v.x, v.y, acc[i][0]);
        UNPK2(v.z, v.w, acc[i][1]);
        v.x += bo; v.y += bo; v.z += bo; v.w += bo;
        *(float4*)(outb + (size_t)o * HW_) = v;
        int gi = i >> 2;
        sg[gi] += v.x + v.y + v.z + v.w;
        qg[gi] += v.x*v.x + v.y*v.y + v.z*v.z + v.w*v.w;
    }
#pragma unroll
    for (int off = 16; off > 0; off >>= 1) {
#pragma unroll
        for (int gi = 0; gi < 4; gi++) {
            sg[gi] += __shfl_xor_sync(0xffffffffu, sg[gi], off);
            qg[gi] += __shfl_xor_sync(0xffffffffu, qg[gi], off);
        }
    }
    if (col == 0) {
        int blk = b*64 + hb;
        float* pp = &g_partial[(size_t)((blk*2 + half)*16)*2];
#pragma unroll
        for (int gi = 0; gi < 4; gi++) {
            int grp = (o0 >> 2) + gi;
            pp[grp*2 + 0] = sg[gi];
            pp[grp*2 + 1] = qg[gi];
        }
    }
}

// ---------------- K3: finalize GN stats ----------------
__global__ void k_stats() {
    int t = threadIdx.x;
    if (t >= 64) return;
    int b = t >> 4, gg = t & 15;
    float s = 0.f, q = 0.f;
    for (int e = 0; e < 128; e++) {
        int blk = b*64 + (e >> 1);
        const float* pp = &g_partial[(size_t)((blk*2 + (e&1))*16 + gg)*2];
        s += pp[0];
        q += pp[1];
    }
    const float N = 4.f * (float)HW_;
    float mu = s / N;
    float var = q / N - mu*mu;
    g_stats[t*2 + 0] = mu;
    g_stats[t*2 + 1] = rsqrtf(var + 1e-5f);
}

// ---------------- K4: GN affine + LeakyReLU ----------------
__global__ void k_norm(float* __restrict__ out,
                       const float* __restrict__ gn_w,
                       const float* __restrict__ gn_b) {
    int i = blockIdx.x * 256 + threadIdx.x;
    int base = i * 4;
    int c = (base >> 14) & 63;
    int b = base >> 20;
    int g = c >> 2;
    float mu  = g_stats[(b*16 + g)*2 + 0];
    float inv = g_stats[(b*16 + g)*2 + 1];
    float sc = gn_w[c] * inv;
    float sh = gn_b[c] - mu * sc;
    float4 v = ((float4*)out)[i];
    v.x = v.x*sc + sh; v.x = (v.x >= 0.f) ? v.x : 0.2f*v.x;
    v.y = v.y*sc + sh; v.y = (v.y >= 0.f) ? v.y : 0.2f*v.y;
    v.z = v.z*sc + sh; v.z = (v.z >= 0.f) ? v.z : 0.2f*v.z;
    v.w = v.w*sc + sh; v.w = (v.w >= 0.f) ? v.w : 0.2f*v.w;
    ((float4*)out)[i] = v;
}

extern "C" void kernel_launch(void* const* d_in, const int* in_sizes, int n_in,
                              void* d_out, int out_size) {
    const float* x     = (const float*)d_in[0];
    const float* w_off = (const float*)d_in[1];
    const float* b_off = (const float*)d_in[2];
    const float* w_def = (const float*)d_in[3];
    const float* b_def = (const float*)d_in[4];
    const float* gn_w  = (const float*)d_in[5];
    const float* gn_b  = (const float*)d_in[6];
    float* out = (float*)d_out;

    cudaFuncSetAttribute(k_main, cudaFuncAttributeMaxDynamicSharedMemorySize,
                         SM_TOTF * (int)sizeof(float));

    k_transpose<<<dim3(HW_/32, C_/32, B_), dim3(32, 32)>>>(x);
    k_wreorder<<<144, 256>>>(w_def);
    k_offconv<<<dim3(H_, B_), 128>>>(x, w_off, b_off);
    k_main<<<dim3(H_/2, B_), 256, SM_TOTF * sizeof(float)>>>(b_def, out);
    k_stats<<<1, 64>>>();
    k_norm<<<4096, 256>>>(out, gn_w, gn_b);
}